// round 1
// baseline (speedup 1.0000x reference)
#include <cuda_runtime.h>

#define TFULL 2048
#define CIN   64
#define DMODEL 128
#define SNUM  3
#define BNUM  2
#define HNUM  8
#define DH    16

// ---------------- wavelet filters (db4-ish, from reference constants) ----------------
__constant__ float c_DEC_LO[8] = {
    -0.010597401784997278f,  0.032883011666982945f,  0.030841381835986965f,
    -0.18703481171888114f,  -0.02798376941698385f,   0.6308807679295904f,
     0.7148465705525415f,    0.23037781330885523f };
__constant__ float c_DEC_HI[8] = {
    -0.23037781330885523f,   0.7148465705525415f,   -0.6308807679295904f,
    -0.02798376941698385f,   0.18703481171888114f,   0.030841381835986965f,
    -0.032883011666982945f, -0.010597401784997278f };

// ---------------- scratch (static device allocations; no cudaMalloc) ----------------
__device__ float g_W   [SNUM*BNUM*TFULL*CIN];      // SWT details (s,b,t,c)
__device__ float g_A   [SNUM*3*DMODEL*CIN];        // composed weights (s,which,e,c)
__device__ float g_cb  [SNUM*3*DMODEL];            // composed biases
__device__ float g_q   [SNUM*BNUM*TFULL*DMODEL];
__device__ float g_k   [SNUM*BNUM*TFULL*DMODEL];
__device__ float g_v   [SNUM*BNUM*TFULL*DMODEL];
__device__ float g_o   [SNUM*BNUM*TFULL*DMODEL];   // attention out, pre out-proj
__device__ float g_meanp[SNUM*BNUM*DMODEL];        // per-(s,b) sums over t
__device__ float g_gate[BNUM*SNUM];

// ================= K0: stationary wavelet transform =================
// grid: B*CIN blocks, one (b, channel) column per block. block: 256.
__global__ void k_swt(const float* __restrict__ x) {
    __shared__ float sh[2][TFULL];
    const int b = blockIdx.x >> 6;       // / 64
    const int c = blockIdx.x & 63;
    const int tid = threadIdx.x;

    for (int t = tid; t < TFULL; t += 256)
        sh[0][t] = x[(b * TFULL + t) * CIN + c];
    __syncthreads();

    int cur = 0;
    for (int j = 0; j < 3; j++) {
        const int step = 1 << j;
        for (int t = tid; t < TFULL; t += 256) {
            float d = 0.f, a = 0.f;
#pragma unroll
            for (int l = 0; l < 8; l++) {
                float val = sh[cur][(t - l * step) & (TFULL - 1)];
                d += val * c_DEC_HI[l];
                a += val * c_DEC_LO[l];
            }
            g_W[(((2 - j) * BNUM + b) * TFULL + t) * CIN + c] = d;
            sh[cur ^ 1][t] = a;
        }
        __syncthreads();
        cur ^= 1;
    }
}

// ================= K1: compose (in_w x Wqkv) weights + biases =================
// grid: (9, 32), block 256. sw = s*3+which.
__global__ void k_compose(const float* __restrict__ Wq, const float* __restrict__ bq,
                          const float* __restrict__ Wk, const float* __restrict__ bk,
                          const float* __restrict__ Wv, const float* __restrict__ bv,
                          const float* __restrict__ in_w, const float* __restrict__ in_b) {
    const int sw = blockIdx.x;
    const int s = sw / 3, w = sw % 3;
    const float* Wx = (w == 0) ? Wq : (w == 1) ? Wk : Wv;
    const float* bx = (w == 0) ? bq : (w == 1) ? bk : bv;

    const int idx = blockIdx.y * 256 + threadIdx.x;   // 0..8191
    const int e = idx >> 6, c = idx & 63;
    const float* iw = in_w + (w * DMODEL + e) * DMODEL;
    const float* wc = Wx + s * DMODEL * CIN + c;
    float acc = 0.f;
#pragma unroll 4
    for (int dd = 0; dd < DMODEL; dd++) acc += iw[dd] * wc[dd * CIN];
    g_A[(sw * DMODEL + e) * CIN + c] = acc;

    if (blockIdx.y == 0 && threadIdx.x < DMODEL) {
        const int ee = threadIdx.x;
        const float* iw2 = in_w + (w * DMODEL + ee) * DMODEL;
        float bb = in_b[w * DMODEL + ee];
#pragma unroll 4
        for (int dd = 0; dd < DMODEL; dd++) bb += iw2[dd] * bx[s * DMODEL + dd];
        g_cb[sw * DMODEL + ee] = bb;
    }
}

// ================= K2: fused q/k/v projection GEMM =================
// out[r][e] = sum_c W[r][c] * A[e][c] + cb[e];  rows = S*B*T = 12288, k = 64.
// grid: (192 row-tiles of 64, 3 which), block 256 (16x16), 4x8 microtile.
__global__ void __launch_bounds__(256) k_qkv() {
    __shared__ float shW[64][33];
    __shared__ float shA[128][33];
    const int row0 = blockIdx.x * 64;
    const int w = blockIdx.y;
    const int s = row0 >> 12;                   // 4096 rows per scale
    const int tid = threadIdx.x;
    const int ty = tid >> 4, tx = tid & 15;
    const float* Abase = g_A + (s * 3 + w) * DMODEL * CIN;

    float acc[4][8];
#pragma unroll
    for (int i = 0; i < 4; i++)
#pragma unroll
        for (int j = 0; j < 8; j++) acc[i][j] = 0.f;

    for (int c0 = 0; c0 < CIN; c0 += 32) {
#pragma unroll
        for (int i = 0; i < 8; i++) {          // 64x32 W tile
            int lin = tid + i * 256;
            shW[lin >> 5][lin & 31] = g_W[(row0 + (lin >> 5)) * CIN + c0 + (lin & 31)];
        }
#pragma unroll
        for (int i = 0; i < 16; i++) {         // 128x32 A tile
            int lin = tid + i * 256;
            shA[lin >> 5][lin & 31] = Abase[(lin >> 5) * CIN + c0 + (lin & 31)];
        }
        __syncthreads();
#pragma unroll
        for (int cc = 0; cc < 32; cc++) {
            float wr[4], ar[8];
#pragma unroll
            for (int i = 0; i < 4; i++) wr[i] = shW[i * 16 + ty][cc];
#pragma unroll
            for (int j = 0; j < 8; j++) ar[j] = shA[j * 16 + tx][cc];
#pragma unroll
            for (int i = 0; i < 4; i++)
#pragma unroll
                for (int j = 0; j < 8; j++) acc[i][j] += wr[i] * ar[j];
        }
        __syncthreads();
    }

    float* out = (w == 0) ? g_q : (w == 1) ? g_k : g_v;
    const float* cb = g_cb + (s * 3 + w) * DMODEL;
#pragma unroll
    for (int i = 0; i < 4; i++) {
        int r = row0 + i * 16 + ty;
#pragma unroll
        for (int j = 0; j < 8; j++) {
            int e = j * 16 + tx;
            out[r * DMODEL + e] = acc[i][j] + cb[e];
        }
    }
}

// ================= K3: flash attention per (s,b,h) =================
// grid: (16 q-tiles, 8 heads, 6 s*b). block 128: one thread per query row.
__global__ void __launch_bounds__(128) k_attn() {
    __shared__ float4 shK[128][4];
    __shared__ float4 shV[128][4];
    const int tid = threadIdx.x;
    const int qt = blockIdx.x, h = blockIdx.y, sb = blockIdx.z;

    const float* qb = g_q + (size_t)sb * TFULL * DMODEL + h * DH;
    const float* kb = g_k + (size_t)sb * TFULL * DMODEL + h * DH;
    const float* vb = g_v + (size_t)sb * TFULL * DMODEL + h * DH;

    const int t = qt * 128 + tid;
    const float sc16 = 0.25f;                  // 1/sqrt(DH)
    float4 q0 = *(const float4*)(qb + t * DMODEL + 0);
    float4 q1 = *(const float4*)(qb + t * DMODEL + 4);
    float4 q2 = *(const float4*)(qb + t * DMODEL + 8);
    float4 q3 = *(const float4*)(qb + t * DMODEL + 12);
    q0.x *= sc16; q0.y *= sc16; q0.z *= sc16; q0.w *= sc16;
    q1.x *= sc16; q1.y *= sc16; q1.z *= sc16; q1.w *= sc16;
    q2.x *= sc16; q2.y *= sc16; q2.z *= sc16; q2.w *= sc16;
    q3.x *= sc16; q3.y *= sc16; q3.z *= sc16; q3.w *= sc16;

    float m = -1e30f, l = 0.f;
    float acc[16];
#pragma unroll
    for (int d = 0; d < 16; d++) acc[d] = 0.f;

    for (int kc = 0; kc < TFULL; kc += 128) {
#pragma unroll
        for (int i = 0; i < 4; i++) {
            int lin = tid + i * 128;           // 512 float4 per buffer
            int r = lin >> 2, jj = lin & 3;
            shK[r][jj] = *(const float4*)(kb + (kc + r) * DMODEL + jj * 4);
            shV[r][jj] = *(const float4*)(vb + (kc + r) * DMODEL + jj * 4);
        }
        __syncthreads();

#pragma unroll 1
        for (int j0 = 0; j0 < 128; j0 += 16) {
            float sc[16];
#pragma unroll
            for (int jj = 0; jj < 16; jj++) {
                float4 ka = shK[j0 + jj][0], kb4 = shK[j0 + jj][1];
                float4 kc4 = shK[j0 + jj][2], kd = shK[j0 + jj][3];
                float s0 = q0.x * ka.x + q0.y * ka.y + q0.z * ka.z + q0.w * ka.w;
                float s1 = q1.x * kb4.x + q1.y * kb4.y + q1.z * kb4.z + q1.w * kb4.w;
                float s2 = q2.x * kc4.x + q2.y * kc4.y + q2.z * kc4.z + q2.w * kc4.w;
                float s3 = q3.x * kd.x + q3.y * kd.y + q3.z * kd.z + q3.w * kd.w;
                sc[jj] = (s0 + s1) + (s2 + s3);
            }
            float mx = m;
#pragma unroll
            for (int jj = 0; jj < 16; jj++) mx = fmaxf(mx, sc[jj]);
            float corr = __expf(m - mx);
            m = mx;
            l *= corr;
#pragma unroll
            for (int d = 0; d < 16; d++) acc[d] *= corr;
#pragma unroll
            for (int jj = 0; jj < 16; jj++) {
                float p = __expf(sc[jj] - mx);
                l += p;
                float4 va = shV[j0 + jj][0], vb4 = shV[j0 + jj][1];
                float4 vc = shV[j0 + jj][2], vd = shV[j0 + jj][3];
                acc[0]  += p * va.x;  acc[1]  += p * va.y;
                acc[2]  += p * va.z;  acc[3]  += p * va.w;
                acc[4]  += p * vb4.x; acc[5]  += p * vb4.y;
                acc[6]  += p * vb4.z; acc[7]  += p * vb4.w;
                acc[8]  += p * vc.x;  acc[9]  += p * vc.y;
                acc[10] += p * vc.z;  acc[11] += p * vc.w;
                acc[12] += p * vd.x;  acc[13] += p * vd.y;
                acc[14] += p * vd.z;  acc[15] += p * vd.w;
            }
        }
        __syncthreads();
    }

    float inv = 1.f / l;
    float* ob = g_o + ((size_t)sb * TFULL + t) * DMODEL + h * DH;
    float4 o0 = make_float4(acc[0] * inv, acc[1] * inv, acc[2] * inv, acc[3] * inv);
    float4 o1 = make_float4(acc[4] * inv, acc[5] * inv, acc[6] * inv, acc[7] * inv);
    float4 o2 = make_float4(acc[8] * inv, acc[9] * inv, acc[10] * inv, acc[11] * inv);
    float4 o3 = make_float4(acc[12] * inv, acc[13] * inv, acc[14] * inv, acc[15] * inv);
    *(float4*)(ob + 0)  = o0;
    *(float4*)(ob + 4)  = o1;
    *(float4*)(ob + 8)  = o2;
    *(float4*)(ob + 12) = o3;
}

// ================= K4: per-(s,b) sum over t (deterministic, no atomics) =================
__global__ void k_meanred() {
    const int s = blockIdx.x, b = blockIdx.y;
    const int d = threadIdx.x;
    const float* base = g_o + ((size_t)(s * BNUM + b) * TFULL) * DMODEL + d;
    float sum = 0.f;
#pragma unroll 8
    for (int t = 0; t < TFULL; t++) sum += base[t * DMODEL];
    g_meanp[(s * BNUM + b) * DMODEL + d] = sum;
}

// ================= K5: gate computation (1 block) =================
__global__ void k_gate(const float* __restrict__ out_w, const float* __restrict__ out_b,
                       const float* __restrict__ gate_w, const float* __restrict__ gate_b) {
    __shared__ float sh_gf[DMODEL];
    __shared__ float sh_lg[SNUM];
    const int d = threadIdx.x;     // 128 threads
    for (int b = 0; b < BNUM; b++) {
        float s = 0.f;
        const float* ow = out_w + d * DMODEL;
#pragma unroll 4
        for (int dd = 0; dd < DMODEL; dd++) {
            float mval = g_meanp[(0 * BNUM + b) * DMODEL + dd]
                       + g_meanp[(1 * BNUM + b) * DMODEL + dd]
                       + g_meanp[(2 * BNUM + b) * DMODEL + dd];
            s += ow[dd] * mval;
        }
        sh_gf[d] = s * (1.0f / (TFULL * SNUM)) + out_b[d];
        __syncthreads();
        if (d < SNUM) {
            float lg = gate_b[d];
            for (int dd = 0; dd < DMODEL; dd++) lg += sh_gf[dd] * gate_w[d * DMODEL + dd];
            sh_lg[d] = lg;
        }
        __syncthreads();
        if (d == 0) {
            float mx = fmaxf(sh_lg[0], fmaxf(sh_lg[1], sh_lg[2]));
            float e0 = __expf(sh_lg[0] - mx);
            float e1 = __expf(sh_lg[1] - mx);
            float e2 = __expf(sh_lg[2] - mx);
            float inv = 1.f / (e0 + e1 + e2);
            g_gate[b * 3 + 0] = e0 * inv;
            g_gate[b * 3 + 1] = e1 * inv;
            g_gate[b * 3 + 2] = e2 * inv;
        }
        __syncthreads();
    }
}

// ================= K6: gated combine + output projection =================
// Z[r][e] = sum_d (sum_s gate[b,s]*o[s,r,d]) * out_w[e][d] + out_b[e]
// grid: 64 row-tiles of 64 over B*T=4096, block 256 (16x16), 4x8 microtile, k=128.
__global__ void __launch_bounds__(256) k_final(const float* __restrict__ out_w,
                                               const float* __restrict__ out_b,
                                               float* __restrict__ Z) {
    __shared__ float shI[64][33];
    __shared__ float shWt[128][33];
    const int row0 = blockIdx.x * 64;          // row in B*T
    const int tid = threadIdx.x;
    const int b = row0 >> 11;                  // 2048 rows per batch
    const float gt0 = g_gate[b * 3 + 0];
    const float gt1 = g_gate[b * 3 + 1];
    const float gt2 = g_gate[b * 3 + 2];
    const int ty = tid >> 4, tx = tid & 15;
    const size_t SB = (size_t)BNUM * TFULL * DMODEL;

    float acc[4][8];
#pragma unroll
    for (int i = 0; i < 4; i++)
#pragma unroll
        for (int j = 0; j < 8; j++) acc[i][j] = 0.f;

    for (int c0 = 0; c0 < DMODEL; c0 += 32) {
#pragma unroll
        for (int i = 0; i < 8; i++) {          // 64x32 combined-input tile
            int lin = tid + i * 256;
            int rr = lin >> 5, cc = lin & 31;
            size_t idx = (size_t)(row0 + rr) * DMODEL + c0 + cc;   // (b,t,d) flattened
            float v0 = g_o[idx];
            float v1 = g_o[SB + idx];
            float v2 = g_o[2 * SB + idx];
            shI[rr][cc] = gt0 * v0 + gt1 * v1 + gt2 * v2;
        }
#pragma unroll
        for (int i = 0; i < 16; i++) {         // 128x32 out_w tile
            int lin = tid + i * 256;
            shWt[lin >> 5][lin & 31] = out_w[(lin >> 5) * DMODEL + c0 + (lin & 31)];
        }
        __syncthreads();
#pragma unroll
        for (int cc = 0; cc < 32; cc++) {
            float ir[4], wr[8];
#pragma unroll
            for (int i = 0; i < 4; i++) ir[i] = shI[i * 16 + ty][cc];
#pragma unroll
            for (int j = 0; j < 8; j++) wr[j] = shWt[j * 16 + tx][cc];
#pragma unroll
            for (int i = 0; i < 4; i++)
#pragma unroll
                for (int j = 0; j < 8; j++) acc[i][j] += ir[i] * wr[j];
        }
        __syncthreads();
    }

#pragma unroll
    for (int i = 0; i < 4; i++) {
        int r = row0 + i * 16 + ty;
#pragma unroll
        for (int j = 0; j < 8; j++) {
            int e = j * 16 + tx;
            Z[(size_t)r * DMODEL + e] = acc[i][j] + out_b[e];
        }
    }
}

// ================= launch =================
extern "C" void kernel_launch(void* const* d_in, const int* in_sizes, int n_in,
                              void* d_out, int out_size) {
    const float* x      = (const float*)d_in[0];
    const float* Wq     = (const float*)d_in[1];
    const float* bq     = (const float*)d_in[2];
    const float* Wk     = (const float*)d_in[3];
    const float* bk     = (const float*)d_in[4];
    const float* Wv     = (const float*)d_in[5];
    const float* bv     = (const float*)d_in[6];
    const float* in_w   = (const float*)d_in[7];
    const float* in_b   = (const float*)d_in[8];
    const float* out_w  = (const float*)d_in[9];
    const float* out_b  = (const float*)d_in[10];
    const float* gate_w = (const float*)d_in[11];
    const float* gate_b = (const float*)d_in[12];
    float* Z = (float*)d_out;

    k_swt    <<<BNUM * CIN, 256>>>(x);
    k_compose<<<dim3(9, 32), 256>>>(Wq, bq, Wk, bk, Wv, bv, in_w, in_b);
    k_qkv    <<<dim3(192, 3), 256>>>();
    k_attn   <<<dim3(16, HNUM, SNUM * BNUM), 128>>>();
    k_meanred<<<dim3(SNUM, BNUM), DMODEL>>>();
    k_gate   <<<1, DMODEL>>>(out_w, out_b, gate_w, gate_b);
    k_final  <<<64, 256>>>(out_w, out_b, Z);
}

// round 2
// speedup vs baseline: 1.3914x; 1.3914x over previous
#include <cuda_runtime.h>

#define TFULL 2048
#define CIN   64
#define DMODEL 128
#define SNUM  3
#define BNUM  2
#define HNUM  8
#define DH    16

typedef unsigned long long u64;

__device__ __forceinline__ u64 pack2(float lo, float hi) {
    u64 r; asm("mov.b64 %0,{%1,%2};" : "=l"(r) : "f"(lo), "f"(hi)); return r;
}
__device__ __forceinline__ void unpack2(u64 v, float& lo, float& hi) {
    asm("mov.b64 {%0,%1},%2;" : "=f"(lo), "=f"(hi) : "l"(v));
}
__device__ __forceinline__ u64 ffma2(u64 a, u64 b, u64 c) {
    u64 d; asm("fma.rn.f32x2 %0,%1,%2,%3;" : "=l"(d) : "l"(a), "l"(b), "l"(c)); return d;
}
__device__ __forceinline__ u64 fmul2(u64 a, u64 b) {
    u64 d; asm("mul.rn.f32x2 %0,%1,%2;" : "=l"(d) : "l"(a), "l"(b)); return d;
}

// ---------------- wavelet filters ----------------
__constant__ float c_DEC_LO[8] = {
    -0.010597401784997278f,  0.032883011666982945f,  0.030841381835986965f,
    -0.18703481171888114f,  -0.02798376941698385f,   0.6308807679295904f,
     0.7148465705525415f,    0.23037781330885523f };
__constant__ float c_DEC_HI[8] = {
    -0.23037781330885523f,   0.7148465705525415f,   -0.6308807679295904f,
    -0.02798376941698385f,   0.18703481171888114f,   0.030841381835986965f,
    -0.032883011666982945f, -0.010597401784997278f };

// ---------------- scratch ----------------
__device__ float g_W   [SNUM*BNUM*TFULL*CIN];
__device__ float g_A   [SNUM*3*DMODEL*CIN];
__device__ float g_cb  [SNUM*3*DMODEL];
__device__ float g_q   [SNUM*BNUM*TFULL*DMODEL];
__device__ float g_k   [SNUM*BNUM*TFULL*DMODEL];
__device__ float g_v   [SNUM*BNUM*TFULL*DMODEL];
__device__ float g_o   [SNUM*BNUM*TFULL*DMODEL];
__device__ float g_meanp[SNUM*BNUM*16*DMODEL];     // partial t-sums
__device__ float g_gate[BNUM*SNUM];

// ================= K0: stationary wavelet transform =================
__global__ void k_swt(const float* __restrict__ x) {
    __shared__ float sh[2][TFULL];
    const int b = blockIdx.x >> 6;
    const int c = blockIdx.x & 63;
    const int tid = threadIdx.x;

    for (int t = tid; t < TFULL; t += 256)
        sh[0][t] = x[(b * TFULL + t) * CIN + c];
    __syncthreads();

    int cur = 0;
    for (int j = 0; j < 3; j++) {
        const int step = 1 << j;
        for (int t = tid; t < TFULL; t += 256) {
            float d = 0.f, a = 0.f;
#pragma unroll
            for (int l = 0; l < 8; l++) {
                float val = sh[cur][(t - l * step) & (TFULL - 1)];
                d += val * c_DEC_HI[l];
                a += val * c_DEC_LO[l];
            }
            g_W[(((2 - j) * BNUM + b) * TFULL + t) * CIN + c] = d;
            sh[cur ^ 1][t] = a;
        }
        __syncthreads();
        cur ^= 1;
    }
}

// ================= K1: compose (in_w x Wqkv) weights + biases =================
__global__ void k_compose(const float* __restrict__ Wq, const float* __restrict__ bq,
                          const float* __restrict__ Wk, const float* __restrict__ bk,
                          const float* __restrict__ Wv, const float* __restrict__ bv,
                          const float* __restrict__ in_w, const float* __restrict__ in_b) {
    const int sw = blockIdx.x;
    const int s = sw / 3, w = sw % 3;
    const float* Wx = (w == 0) ? Wq : (w == 1) ? Wk : Wv;
    const float* bx = (w == 0) ? bq : (w == 1) ? bk : bv;

    const int idx = blockIdx.y * 256 + threadIdx.x;
    const int e = idx >> 6, c = idx & 63;
    const float* iw = in_w + (w * DMODEL + e) * DMODEL;
    const float* wc = Wx + s * DMODEL * CIN + c;
    float acc = 0.f;
#pragma unroll 4
    for (int dd = 0; dd < DMODEL; dd++) acc += iw[dd] * wc[dd * CIN];
    g_A[(sw * DMODEL + e) * CIN + c] = acc;

    if (blockIdx.y == 0 && threadIdx.x < DMODEL) {
        const int ee = threadIdx.x;
        const float* iw2 = in_w + (w * DMODEL + ee) * DMODEL;
        float bb = in_b[w * DMODEL + ee];
#pragma unroll 4
        for (int dd = 0; dd < DMODEL; dd++) bb += iw2[dd] * bx[s * DMODEL + dd];
        g_cb[sw * DMODEL + ee] = bb;
    }
}

// ================= K2: fused q/k/v projection GEMM =================
__global__ void __launch_bounds__(256) k_qkv() {
    __shared__ float shW[64][33];
    __shared__ float shA[128][33];
    const int row0 = blockIdx.x * 64;
    const int w = blockIdx.y;
    const int s = row0 >> 12;
    const int tid = threadIdx.x;
    const int ty = tid >> 4, tx = tid & 15;
    const float* Abase = g_A + (s * 3 + w) * DMODEL * CIN;

    float acc[4][8];
#pragma unroll
    for (int i = 0; i < 4; i++)
#pragma unroll
        for (int j = 0; j < 8; j++) acc[i][j] = 0.f;

    for (int c0 = 0; c0 < CIN; c0 += 32) {
#pragma unroll
        for (int i = 0; i < 8; i++) {
            int lin = tid + i * 256;
            shW[lin >> 5][lin & 31] = g_W[(row0 + (lin >> 5)) * CIN + c0 + (lin & 31)];
        }
#pragma unroll
        for (int i = 0; i < 16; i++) {
            int lin = tid + i * 256;
            shA[lin >> 5][lin & 31] = Abase[(lin >> 5) * CIN + c0 + (lin & 31)];
        }
        __syncthreads();
#pragma unroll
        for (int cc = 0; cc < 32; cc++) {
            float wr[4], ar[8];
#pragma unroll
            for (int i = 0; i < 4; i++) wr[i] = shW[i * 16 + ty][cc];
#pragma unroll
            for (int j = 0; j < 8; j++) ar[j] = shA[j * 16 + tx][cc];
#pragma unroll
            for (int i = 0; i < 4; i++)
#pragma unroll
                for (int j = 0; j < 8; j++) acc[i][j] += wr[i] * ar[j];
        }
        __syncthreads();
    }

    float* out = (w == 0) ? g_q : (w == 1) ? g_k : g_v;
    const float* cb = g_cb + (s * 3 + w) * DMODEL;
#pragma unroll
    for (int i = 0; i < 4; i++) {
        int r = row0 + i * 16 + ty;
#pragma unroll
        for (int j = 0; j < 8; j++) {
            int e = j * 16 + tx;
            out[r * DMODEL + e] = acc[i][j] + cb[e];
        }
    }
}

// ================= K3: flash attention, 2 queries/thread, f32x2 packed =================
// grid: (8 q-tiles of 256, 8 heads, 6 s*b). block 128.
__global__ void __launch_bounds__(128) k_attn() {
    __shared__ float4 shK4[128][4];
    __shared__ float4 shV4[128][4];
    const int tid = threadIdx.x;
    const int qt = blockIdx.x, h = blockIdx.y, sb = blockIdx.z;

    const float* qb = g_q + (size_t)sb * TFULL * DMODEL + h * DH;
    const float* kb = g_k + (size_t)sb * TFULL * DMODEL + h * DH;
    const float* vb = g_v + (size_t)sb * TFULL * DMODEL + h * DH;

    const float sc = 0.25f * 1.4426950408889634f;   // 1/sqrt(16) * log2(e)
    const int t0 = qt * 256 + tid;
    const int t1 = t0 + 128;

    u64 qp[2][8];
#pragma unroll
    for (int qi = 0; qi < 2; qi++) {
        const float* qr = qb + (size_t)(qi ? t1 : t0) * DMODEL;
#pragma unroll
        for (int i = 0; i < 4; i++) {
            float4 a = *(const float4*)(qr + i * 4);
            qp[qi][i * 2 + 0] = pack2(a.x * sc, a.y * sc);
            qp[qi][i * 2 + 1] = pack2(a.z * sc, a.w * sc);
        }
    }

    float m0 = -1e30f, m1 = -1e30f, l0 = 0.f, l1 = 0.f;
    u64 acc0[8], acc1[8];
    const u64 zz = pack2(0.f, 0.f);
#pragma unroll
    for (int i = 0; i < 8; i++) { acc0[i] = zz; acc1[i] = zz; }

    for (int kc = 0; kc < TFULL; kc += 128) {
#pragma unroll
        for (int i = 0; i < 4; i++) {
            int lin = tid + i * 128;
            int r = lin >> 2, c = lin & 3;
            shK4[r][c] = *(const float4*)(kb + (size_t)(kc + r) * DMODEL + c * 4);
            shV4[r][c] = *(const float4*)(vb + (size_t)(kc + r) * DMODEL + c * 4);
        }
        __syncthreads();

#pragma unroll 1
        for (int j0 = 0; j0 < 128; j0 += 16) {
            float s0[16], s1[16];
#pragma unroll
            for (int jj = 0; jj < 16; jj++) {
                const ulonglong2* kr = (const ulonglong2*)&shK4[j0 + jj][0];
                ulonglong2 ka = kr[0], kb2 = kr[1], kc2 = kr[2], kd = kr[3];
                u64 a0 = fmul2(qp[0][0], ka.x);
                a0 = ffma2(qp[0][1], ka.y, a0);
                a0 = ffma2(qp[0][2], kb2.x, a0);
                a0 = ffma2(qp[0][3], kb2.y, a0);
                a0 = ffma2(qp[0][4], kc2.x, a0);
                a0 = ffma2(qp[0][5], kc2.y, a0);
                a0 = ffma2(qp[0][6], kd.x, a0);
                a0 = ffma2(qp[0][7], kd.y, a0);
                u64 a1 = fmul2(qp[1][0], ka.x);
                a1 = ffma2(qp[1][1], ka.y, a1);
                a1 = ffma2(qp[1][2], kb2.x, a1);
                a1 = ffma2(qp[1][3], kb2.y, a1);
                a1 = ffma2(qp[1][4], kc2.x, a1);
                a1 = ffma2(qp[1][5], kc2.y, a1);
                a1 = ffma2(qp[1][6], kd.x, a1);
                a1 = ffma2(qp[1][7], kd.y, a1);
                float lo, hi;
                unpack2(a0, lo, hi); s0[jj] = lo + hi;
                unpack2(a1, lo, hi); s1[jj] = lo + hi;
            }
            // online softmax update
            float mx0 = m0, mx1 = m1;
#pragma unroll
            for (int jj = 0; jj < 16; jj++) { mx0 = fmaxf(mx0, s0[jj]); mx1 = fmaxf(mx1, s1[jj]); }
            float c0 = exp2f(m0 - mx0), c1 = exp2f(m1 - mx1);
            m0 = mx0; m1 = mx1;
            l0 *= c0; l1 *= c1;
            u64 cp0 = pack2(c0, c0), cp1 = pack2(c1, c1);
#pragma unroll
            for (int i = 0; i < 8; i++) { acc0[i] = fmul2(acc0[i], cp0); acc1[i] = fmul2(acc1[i], cp1); }
#pragma unroll
            for (int jj = 0; jj < 16; jj++) {
                float p0 = exp2f(s0[jj] - m0);
                float p1 = exp2f(s1[jj] - m1);
                l0 += p0; l1 += p1;
                s0[jj] = p0; s1[jj] = p1;
            }
#pragma unroll
            for (int jj = 0; jj < 16; jj++) {
                const ulonglong2* vr = (const ulonglong2*)&shV4[j0 + jj][0];
                ulonglong2 va = vr[0], vb2 = vr[1], vc = vr[2], vd = vr[3];
                u64 pp0 = pack2(s0[jj], s0[jj]);
                u64 pp1 = pack2(s1[jj], s1[jj]);
                acc0[0] = ffma2(pp0, va.x, acc0[0]);
                acc0[1] = ffma2(pp0, va.y, acc0[1]);
                acc0[2] = ffma2(pp0, vb2.x, acc0[2]);
                acc0[3] = ffma2(pp0, vb2.y, acc0[3]);
                acc0[4] = ffma2(pp0, vc.x, acc0[4]);
                acc0[5] = ffma2(pp0, vc.y, acc0[5]);
                acc0[6] = ffma2(pp0, vd.x, acc0[6]);
                acc0[7] = ffma2(pp0, vd.y, acc0[7]);
                acc1[0] = ffma2(pp1, va.x, acc1[0]);
                acc1[1] = ffma2(pp1, va.y, acc1[1]);
                acc1[2] = ffma2(pp1, vb2.x, acc1[2]);
                acc1[3] = ffma2(pp1, vb2.y, acc1[3]);
                acc1[4] = ffma2(pp1, vc.x, acc1[4]);
                acc1[5] = ffma2(pp1, vc.y, acc1[5]);
                acc1[6] = ffma2(pp1, vd.x, acc1[6]);
                acc1[7] = ffma2(pp1, vd.y, acc1[7]);
            }
        }
        __syncthreads();
    }

#pragma unroll
    for (int qi = 0; qi < 2; qi++) {
        const u64* ac = qi ? acc1 : acc0;
        float inv = 1.f / (qi ? l1 : l0);
        float* ob = g_o + ((size_t)sb * TFULL + (qi ? t1 : t0)) * DMODEL + h * DH;
#pragma unroll
        for (int i = 0; i < 4; i++) {
            float x0, y0, x1, y1;
            unpack2(ac[i * 2 + 0], x0, y0);
            unpack2(ac[i * 2 + 1], x1, y1);
            *(float4*)(ob + i * 4) = make_float4(x0 * inv, y0 * inv, x1 * inv, y1 * inv);
        }
    }
}

// ================= K4: partial t-sums (deterministic, no atomics) =================
// grid (S, B, 16 chunks of 128 t), block 128 = one d each.
__global__ void k_meanred() {
    const int s = blockIdx.x, b = blockIdx.y, ch = blockIdx.z;
    const int d = threadIdx.x;
    const float* base = g_o + (((size_t)(s * BNUM + b) * TFULL) + ch * 128) * DMODEL + d;
    float sum = 0.f;
#pragma unroll 8
    for (int t = 0; t < 128; t++) sum += base[t * DMODEL];
    g_meanp[((s * BNUM + b) * 16 + ch) * DMODEL + d] = sum;
}

// ================= K5: gate computation (1 block) =================
__global__ void k_gate(const float* __restrict__ out_w, const float* __restrict__ out_b,
                       const float* __restrict__ gate_w, const float* __restrict__ gate_b) {
    __shared__ float sh_m[DMODEL];
    __shared__ float sh_gf[DMODEL];
    __shared__ float sh_lg[SNUM];
    const int d = threadIdx.x;
    for (int b = 0; b < BNUM; b++) {
        float mv = 0.f;
#pragma unroll
        for (int s = 0; s < SNUM; s++)
#pragma unroll
            for (int c = 0; c < 16; c++)
                mv += g_meanp[((s * BNUM + b) * 16 + c) * DMODEL + d];
        sh_m[d] = mv;
        __syncthreads();
        float acc = 0.f;
        const float* ow = out_w + d * DMODEL;
#pragma unroll 4
        for (int dd = 0; dd < DMODEL; dd++) acc += ow[dd] * sh_m[dd];
        sh_gf[d] = acc * (1.0f / (TFULL * SNUM)) + out_b[d];
        __syncthreads();
        if (d < SNUM) {
            float lg = gate_b[d];
            for (int dd = 0; dd < DMODEL; dd++) lg += sh_gf[dd] * gate_w[d * DMODEL + dd];
            sh_lg[d] = lg;
        }
        __syncthreads();
        if (d == 0) {
            float mx = fmaxf(sh_lg[0], fmaxf(sh_lg[1], sh_lg[2]));
            float e0 = __expf(sh_lg[0] - mx);
            float e1 = __expf(sh_lg[1] - mx);
            float e2 = __expf(sh_lg[2] - mx);
            float inv = 1.f / (e0 + e1 + e2);
            g_gate[b * 3 + 0] = e0 * inv;
            g_gate[b * 3 + 1] = e1 * inv;
            g_gate[b * 3 + 2] = e2 * inv;
        }
        __syncthreads();
    }
}

// ================= K6: gated combine + output projection =================
__global__ void __launch_bounds__(256) k_final(const float* __restrict__ out_w,
                                               const float* __restrict__ out_b,
                                               float* __restrict__ Z) {
    __shared__ float shI[64][33];
    __shared__ float shWt[128][33];
    const int row0 = blockIdx.x * 64;
    const int tid = threadIdx.x;
    const int b = row0 >> 11;
    const float gt0 = g_gate[b * 3 + 0];
    const float gt1 = g_gate[b * 3 + 1];
    const float gt2 = g_gate[b * 3 + 2];
    const int ty = tid >> 4, tx = tid & 15;
    const size_t SB = (size_t)BNUM * TFULL * DMODEL;

    float acc[4][8];
#pragma unroll
    for (int i = 0; i < 4; i++)
#pragma unroll
        for (int j = 0; j < 8; j++) acc[i][j] = 0.f;

    for (int c0 = 0; c0 < DMODEL; c0 += 32) {
#pragma unroll
        for (int i = 0; i < 8; i++) {
            int lin = tid + i * 256;
            int rr = lin >> 5, cc = lin & 31;
            size_t idx = (size_t)(row0 + rr) * DMODEL + c0 + cc;
            float v0 = g_o[idx];
            float v1 = g_o[SB + idx];
            float v2 = g_o[2 * SB + idx];
            shI[rr][cc] = gt0 * v0 + gt1 * v1 + gt2 * v2;
        }
#pragma unroll
        for (int i = 0; i < 16; i++) {
            int lin = tid + i * 256;
            shWt[lin >> 5][lin & 31] = out_w[(lin >> 5) * DMODEL + c0 + (lin & 31)];
        }
        __syncthreads();
#pragma unroll
        for (int cc = 0; cc < 32; cc++) {
            float ir[4], wr[8];
#pragma unroll
            for (int i = 0; i < 4; i++) ir[i] = shI[i * 16 + ty][cc];
#pragma unroll
            for (int j = 0; j < 8; j++) wr[j] = shWt[j * 16 + tx][cc];
#pragma unroll
            for (int i = 0; i < 4; i++)
#pragma unroll
                for (int j = 0; j < 8; j++) acc[i][j] += ir[i] * wr[j];
        }
        __syncthreads();
    }

#pragma unroll
    for (int i = 0; i < 4; i++) {
        int r = row0 + i * 16 + ty;
#pragma unroll
        for (int j = 0; j < 8; j++) {
            int e = j * 16 + tx;
            Z[(size_t)r * DMODEL + e] = acc[i][j] + out_b[e];
        }
    }
}

// ================= launch =================
extern "C" void kernel_launch(void* const* d_in, const int* in_sizes, int n_in,
                              void* d_out, int out_size) {
    const float* x      = (const float*)d_in[0];
    const float* Wq     = (const float*)d_in[1];
    const float* bq     = (const float*)d_in[2];
    const float* Wk     = (const float*)d_in[3];
    const float* bk     = (const float*)d_in[4];
    const float* Wv     = (const float*)d_in[5];
    const float* bv     = (const float*)d_in[6];
    const float* in_w   = (const float*)d_in[7];
    const float* in_b   = (const float*)d_in[8];
    const float* out_w  = (const float*)d_in[9];
    const float* out_b  = (const float*)d_in[10];
    const float* gate_w = (const float*)d_in[11];
    const float* gate_b = (const float*)d_in[12];
    float* Z = (float*)d_out;

    k_swt    <<<BNUM * CIN, 256>>>(x);
    k_compose<<<dim3(9, 32), 256>>>(Wq, bq, Wk, bk, Wv, bv, in_w, in_b);
    k_qkv    <<<dim3(192, 3), 256>>>();
    k_attn   <<<dim3(8, HNUM, SNUM * BNUM), 128>>>();
    k_meanred<<<dim3(SNUM, BNUM, 16), 128>>>();
    k_gate   <<<1, DMODEL>>>(out_w, out_b, gate_w, gate_b);
    k_final  <<<64, 256>>>(out_w, out_b, Z);
}